// round 1
// baseline (speedup 1.0000x reference)
#include <cuda_runtime.h>
#include <math.h>
#include <stdint.h>

// ---------------- problem constants ----------------
#define TT      512          // sequence length
#define UDIM    512          // LSTM hidden
#define NGATE   2048         // 4*U
#define XDIM    250          // word(200)+tag(50)
#define HID     1024
#define NSP     8192         // spans per head
#define KS_     4
#define KL_     3
#define TSZ     (TT*HID)     // one P table
#define GDIR    64           // CTAs per LSTM direction
#define UPC     8            // units per CTA (512/64)

// ---------------- device scratch (static; no allocation allowed) ----------------
__device__ float g_x   [TT*XDIM];
__device__ float g_xg  [4*TT*NGATE];     // gate preactivations (incl bias) per direction
__device__ float g_H0  [TT*1024];        // layer0 output [fwd|bwd]
__device__ float g_OUTF[TT*UDIM];        // layer1 fwd h
__device__ float g_OUTB[TT*UDIM];        // layer1 bwd h
__device__ float g_P   [14*TSZ];         // factorized span tables
__device__ float g_loss;
__device__ unsigned g_cnt2[2];
__device__ unsigned g_gen2[2];

// ---------------- per-direction grid barrier ----------------
__device__ __forceinline__ void dir_sync(int d, unsigned n) {
    __syncthreads();
    if (threadIdx.x == 0) {
        __threadfence();
        volatile unsigned* genp = (volatile unsigned*)&g_gen2[d];
        unsigned my = *genp;
        if (atomicAdd(&g_cnt2[d], 1u) == n - 1u) {
            g_cnt2[d] = 0u;
            __threadfence();
            atomicAdd(&g_gen2[d], 1u);
        } else {
            while (*genp == my) { __nanosleep(20); }
        }
        __threadfence();
    }
    __syncthreads();
}

// ---------------- misc kernels ----------------
__global__ void zero_kernel() {
    g_loss = 0.f;
    g_cnt2[0] = 0u; g_cnt2[1] = 0u;
}

__global__ void build_x_kernel(const int* __restrict__ wi, const int* __restrict__ ti,
                               const float* __restrict__ Ww, const float* __restrict__ Wt) {
    int t = blockIdx.x;
    int j = threadIdx.x;
    if (j < 200)      g_x[t*XDIM + j] = Ww[(size_t)wi[t]*200 + j];
    else if (j < XDIM) g_x[t*XDIM + j] = Wt[(size_t)ti[t]*50 + (j - 200)];
}

__global__ void finalize_kernel(float* out) {
    out[0] = g_loss * (1.0f / 16384.0f);
}

// ---------------- batched SGEMM: C = A(MxK) * B(NxK)^T (+bias[n]) ----------------
// BM=64, BN=128, BK=16, 256 threads, TM=4, TN=8
struct GemmDesc {
    const float* A; const float* B; float* C; const float* bias;
    int M, N, K, lda, ldb, ldc;
};
struct GemmBatch { GemmDesc d[14]; };

__global__ void __launch_bounds__(256)
sgemm_kernel(GemmBatch batch)
{
    GemmDesc g = batch.d[blockIdx.z];
    const int m0 = blockIdx.y * 64;
    const int n0 = blockIdx.x * 128;
    if (m0 >= g.M || n0 >= g.N) return;

    __shared__ float As[16][68];
    __shared__ float Bs[16][132];

    const int tid = threadIdx.x;
    const int tx = tid & 15;   // n tile: 16 threads * 8
    const int ty = tid >> 4;   // m tile: 16 threads * 4

    float acc[4][8];
    #pragma unroll
    for (int i = 0; i < 4; i++)
        #pragma unroll
        for (int j = 0; j < 8; j++) acc[i][j] = 0.f;

    for (int k0 = 0; k0 < g.K; k0 += 16) {
        // load A tile (64m x 16k): thread -> m=tid/4, k=(tid&3)*4 + q
        {
            int m = tid >> 2;
            int kk = (tid & 3) * 4;
            const float* ap = g.A + (size_t)(m0 + m) * g.lda + k0 + kk;
            #pragma unroll
            for (int q = 0; q < 4; q++) {
                float v = (k0 + kk + q < g.K) ? ap[q] : 0.f;
                As[kk + q][m] = v;
            }
        }
        // load B tile (128n x 16k): thread -> n=tid/2, k=(tid&1)*8 + q
        {
            int n = tid >> 1;
            int kk = (tid & 1) * 8;
            const float* bp = g.B + (size_t)(n0 + n) * g.ldb + k0 + kk;
            #pragma unroll
            for (int q = 0; q < 8; q++) {
                float v = (k0 + kk + q < g.K) ? bp[q] : 0.f;
                Bs[kk + q][n] = v;
            }
        }
        __syncthreads();

        #pragma unroll
        for (int kk = 0; kk < 16; kk++) {
            float a[4], b[8];
            *(float4*)a      = *(const float4*)&As[kk][ty * 4];
            *(float4*)&b[0]  = *(const float4*)&Bs[kk][tx * 8];
            *(float4*)&b[4]  = *(const float4*)&Bs[kk][tx * 8 + 4];
            #pragma unroll
            for (int i = 0; i < 4; i++)
                #pragma unroll
                for (int j = 0; j < 8; j++)
                    acc[i][j] = fmaf(a[i], b[j], acc[i][j]);
        }
        __syncthreads();
    }

    #pragma unroll
    for (int i = 0; i < 4; i++) {
        float* cp = g.C + (size_t)(m0 + ty * 4 + i) * g.ldc + n0 + tx * 8;
        float o[8];
        #pragma unroll
        for (int j = 0; j < 8; j++) {
            float v = acc[i][j];
            if (g.bias) v += g.bias[n0 + tx * 8 + j];
            o[j] = v;
        }
        *(float4*)cp       = *(float4*)&o[0];
        *(float4*)(cp + 4) = *(float4*)&o[4];
    }
}

// ---------------- persistent bidirectional LSTM layer ----------------
// 128 CTAs: blocks [0,64) forward, [64,128) backward. Each CTA owns 8 units
// (32 gate rows). Recurrent weights live in registers (64 floats/thread).
__global__ void __launch_bounds__(256, 1)
lstm_kernel(const float* __restrict__ xgF, const float* __restrict__ xgB,
            const float* __restrict__ WhhF, const float* __restrict__ WhhB,
            float* outF, int strideF, int ocolF,
            float* outB, int strideB, int ocolB)
{
    const int tid = threadIdx.x;
    const int bid = blockIdx.x;
    const bool back = (bid >= GDIR);
    const int dsel  = back ? 1 : 0;
    const int dd    = back ? bid - GDIR : bid;

    const float* xg   = back ? xgB   : xgF;
    const float* Whh  = back ? WhhB  : WhhF;
    float*       out  = back ? outB  : outF;
    const int ostride = back ? strideB : strideF;
    const int ocol    = back ? ocolB  : ocolF;

    const int row   = tid >> 3;   // 0..31  (gate*8 + unit_local)
    const int chunk = tid & 7;    // 0..7   (64-wide k chunk)
    const int gate  = row >> 3;
    const int ul    = row & 7;
    const int u0    = dd * UPC;
    const int ug    = u0 + ul;
    const int grow  = gate * UDIM + ug;

    // preload recurrent weights into registers
    float4 w[16];
    {
        const float4* wp = (const float4*)(Whh + (size_t)grow * UDIM + chunk * 64);
        #pragma unroll
        for (int q = 0; q < 16; q++) w[q] = wp[q];
    }

    __shared__ float gs[32];
    float c = 0.f;
    const float* hbase = out + ocol;

    for (int s = 0; s < TT; s++) {
        const int t = back ? (TT - 1 - s) : s;
        float a0 = 0.f, a1 = 0.f, a2 = 0.f, a3 = 0.f;
        if (s > 0) {
            const int tp = back ? t + 1 : t - 1;
            const float4* hp = (const float4*)(hbase + (size_t)tp * ostride + chunk * 64);
            #pragma unroll
            for (int q = 0; q < 16; q++) {
                float4 hv = __ldcg(hp + q);
                a0 = fmaf(w[q].x, hv.x, a0);
                a1 = fmaf(w[q].y, hv.y, a1);
                a2 = fmaf(w[q].z, hv.z, a2);
                a3 = fmaf(w[q].w, hv.w, a3);
            }
        }
        float acc = (a0 + a1) + (a2 + a3);
        acc += __shfl_xor_sync(0xffffffffu, acc, 1);
        acc += __shfl_xor_sync(0xffffffffu, acc, 2);
        acc += __shfl_xor_sync(0xffffffffu, acc, 4);
        if (chunk == 0) gs[row] = acc;
        __syncthreads();

        if (tid < UPC) {
            const int u = u0 + tid;
            const float* xr = xg + (size_t)t * NGATE;
            float gi = xr[0 * UDIM + u] + gs[0 * 8 + tid];
            float gf = xr[1 * UDIM + u] + gs[1 * 8 + tid];
            float gg = xr[2 * UDIM + u] + gs[2 * 8 + tid];
            float go = xr[3 * UDIM + u] + gs[3 * 8 + tid];
            float iv = 1.f / (1.f + expf(-gi));
            float fv = 1.f / (1.f + expf(-gf));
            float gv = tanhf(gg);
            float ov = 1.f / (1.f + expf(-go));
            c = fv * c + iv * gv;
            float h = ov * tanhf(c);
            out[(size_t)t * ostride + ocol + u] = h;
        }
        dir_sync(dsel, GDIR);
    }
}

// ---------------- span loss: warp per span, gather from P tables ----------------
template<int KF, int NC>
__global__ void __launch_bounds__(256)
span_kernel(const int* __restrict__ lefts, const int* __restrict__ rights,
            const int* __restrict__ targets,
            const float* __restrict__ b1, const float* __restrict__ W2,
            const float* __restrict__ b2, int tabF, int tabB)
{
    const int warp = (blockIdx.x * blockDim.x + threadIdx.x) >> 5;
    const int lane = threadIdx.x & 31;
    const int wInB = threadIdx.x >> 5;

    float4 acc[8];
    #pragma unroll
    for (int m = 0; m < 8; m++)
        acc[m] = *(const float4*)(b1 + m * 128 + lane * 4);

    int ls[KF], rs[KF];
    #pragma unroll
    for (int k = 0; k < KF; k++) {
        ls[k] = __ldg(lefts  + (size_t)warp * KF + k);
        rs[k] = __ldg(rights + (size_t)warp * KF + k);
    }

    #pragma unroll
    for (int k = 0; k < KF; k++) {
        const float* Pf = g_P + (size_t)(tabF + k) * TSZ;
        const float* Pb = g_P + (size_t)(tabB + k) * TSZ;
        const float* r0 = Pf + (size_t)rs[k]       * HID + lane * 4;  // +
        const float* r1 = Pf + (size_t)(ls[k] - 1) * HID + lane * 4;  // -
        const float* r2 = Pb + (size_t)ls[k]       * HID + lane * 4;  // +
        const float* r3 = Pb + (size_t)(rs[k] + 1) * HID + lane * 4;  // -
        #pragma unroll
        for (int m = 0; m < 8; m++) {
            float4 va = __ldg((const float4*)(r0 + m * 128));
            float4 vb = __ldg((const float4*)(r1 + m * 128));
            float4 vc = __ldg((const float4*)(r2 + m * 128));
            float4 vd = __ldg((const float4*)(r3 + m * 128));
            acc[m].x += (va.x - vb.x) + (vc.x - vd.x);
            acc[m].y += (va.y - vb.y) + (vc.y - vd.y);
            acc[m].z += (va.z - vb.z) + (vc.z - vd.z);
            acc[m].w += (va.w - vb.w) + (vc.w - vd.w);
        }
    }
    #pragma unroll
    for (int m = 0; m < 8; m++) {
        acc[m].x = fmaxf(acc[m].x, 0.f);
        acc[m].y = fmaxf(acc[m].y, 0.f);
        acc[m].z = fmaxf(acc[m].z, 0.f);
        acc[m].w = fmaxf(acc[m].w, 0.f);
    }

    const int tgt = __ldg(targets + warp);
    float mx = -1e30f, ssum = 0.f, sct = 0.f;
    for (int s = 0; s < NC; s++) {
        const float* wr = W2 + (size_t)s * HID + lane * 4;
        float p = 0.f;
        #pragma unroll
        for (int m = 0; m < 8; m++) {
            float4 wv = __ldg((const float4*)(wr + m * 128));
            p += wv.x * acc[m].x + wv.y * acc[m].y + wv.z * acc[m].z + wv.w * acc[m].w;
        }
        p += __shfl_xor_sync(0xffffffffu, p, 1);
        p += __shfl_xor_sync(0xffffffffu, p, 2);
        p += __shfl_xor_sync(0xffffffffu, p, 4);
        p += __shfl_xor_sync(0xffffffffu, p, 8);
        p += __shfl_xor_sync(0xffffffffu, p, 16);
        p += b2[s];
        if (s == tgt) sct = p;
        float m2 = fmaxf(mx, p);
        ssum = ssum * expf(mx - m2) + expf(p - m2);
        mx = m2;
    }
    float loss = mx + logf(ssum) - sct;

    __shared__ float smloss[8];
    if (lane == 0) smloss[wInB] = loss;
    __syncthreads();
    if (threadIdx.x == 0) {
        float s = 0.f;
        #pragma unroll
        for (int q = 0; q < 8; q++) s += smloss[q];
        atomicAdd(&g_loss, s);
    }
}

// ---------------- host launch ----------------
extern "C" void kernel_launch(void* const* d_in, const int* in_sizes, int n_in,
                              void* d_out, int out_size)
{
    (void)n_in; (void)out_size;
    const int* wi = (const int*)d_in[0];
    const int* ti = (const int*)d_in[1];

    // resolve input ordering at runtime (dict-insertion vs reference-arg order)
    int isl, isr, ist, ill, ilr, ilt;
    if (in_sizes[2] == NSP) {          // dict order: struct_targets at index 2
        ist = 2; ilt = 3; isl = 4; isr = 5; ill = 6; ilr = 7;
    } else {                            // arg order: struct_lefts at index 2
        isl = 2; isr = 3; ist = 4; ill = 5; ilr = 6; ilt = 7;
    }

    const float* W_word = (const float*)d_in[8];
    const float* W_tag  = (const float*)d_in[9];
    const float* Wih[4] = {(const float*)d_in[10], (const float*)d_in[13],
                           (const float*)d_in[16], (const float*)d_in[19]};
    const float* Whh[4] = {(const float*)d_in[11], (const float*)d_in[14],
                           (const float*)d_in[17], (const float*)d_in[20]};
    const float* bb [4] = {(const float*)d_in[12], (const float*)d_in[15],
                           (const float*)d_in[18], (const float*)d_in[21]};
    const float* Ws1 = (const float*)d_in[22];
    const float* bs1 = (const float*)d_in[23];
    const float* Ws2 = (const float*)d_in[24];
    const float* bs2 = (const float*)d_in[25];
    const float* Wl1 = (const float*)d_in[26];
    const float* bl1 = (const float*)d_in[27];
    const float* Wl2 = (const float*)d_in[28];
    const float* bl2 = (const float*)d_in[29];

    float *px, *pxg, *pH0, *pOF, *pOB, *pP;
    cudaGetSymbolAddress((void**)&px,  g_x);
    cudaGetSymbolAddress((void**)&pxg, g_xg);
    cudaGetSymbolAddress((void**)&pH0, g_H0);
    cudaGetSymbolAddress((void**)&pOF, g_OUTF);
    cudaGetSymbolAddress((void**)&pOB, g_OUTB);
    cudaGetSymbolAddress((void**)&pP,  g_P);

    zero_kernel<<<1, 1>>>();
    build_x_kernel<<<TT, 256>>>(wi, ti, W_word, W_tag);

    // layer0 gate preactivations: xg = x @ Wih^T + b   (2 directions batched)
    {
        GemmBatch gb = {};
        for (int d = 0; d < 2; d++)
            gb.d[d] = { px, Wih[d], pxg + (size_t)d * TT * NGATE, bb[d],
                        TT, NGATE, XDIM, XDIM, XDIM, NGATE };
        sgemm_kernel<<<dim3(16, 8, 2), 256>>>(gb);
    }
    lstm_kernel<<<2 * GDIR, 256>>>(pxg, pxg + (size_t)TT * NGATE,
                                   Whh[0], Whh[1],
                                   pH0, 1024, 0, pH0, 1024, 512);
    // layer1 gate preactivations from H0
    {
        GemmBatch gb = {};
        for (int d = 0; d < 2; d++)
            gb.d[d] = { pH0, Wih[2 + d], pxg + (size_t)(2 + d) * TT * NGATE, bb[2 + d],
                        TT, NGATE, 1024, 1024, 1024, NGATE };
        sgemm_kernel<<<dim3(16, 8, 2), 256>>>(gb);
    }
    lstm_kernel<<<2 * GDIR, 256>>>(pxg + (size_t)2 * TT * NGATE, pxg + (size_t)3 * TT * NGATE,
                                   Whh[2], Whh[3],
                                   pOF, 512, 0, pOB, 512, 0);

    // factorized span tables: P_k = out_dir @ W1_block_k^T  (14 batched GEMMs)
    {
        GemmBatch gb = {};
        for (int k = 0; k < KS_; k++) {
            gb.d[k]       = { pOF, Ws1 + k * 512,             pP + (size_t)k * TSZ,        nullptr,
                              TT, HID, 512, 512, 4096, HID };
            gb.d[4 + k]   = { pOB, Ws1 + 2048 + k * 512,      pP + (size_t)(4 + k) * TSZ,  nullptr,
                              TT, HID, 512, 512, 4096, HID };
        }
        for (int k = 0; k < KL_; k++) {
            gb.d[8 + k]   = { pOF, Wl1 + k * 512,             pP + (size_t)(8 + k) * TSZ,  nullptr,
                              TT, HID, 512, 512, 3072, HID };
            gb.d[11 + k]  = { pOB, Wl1 + 1536 + k * 512,      pP + (size_t)(11 + k) * TSZ, nullptr,
                              TT, HID, 512, 512, 3072, HID };
        }
        sgemm_kernel<<<dim3(8, 8, 14), 256>>>(gb);
    }

    span_kernel<KS_, 2 ><<<NSP / 8, 256>>>((const int*)d_in[isl], (const int*)d_in[isr],
                                           (const int*)d_in[ist], bs1, Ws2, bs2, 0, 4);
    span_kernel<KL_, 56><<<NSP / 8, 256>>>((const int*)d_in[ill], (const int*)d_in[ilr],
                                           (const int*)d_in[ilt], bl1, Wl2, bl2, 8, 11);

    finalize_kernel<<<1, 1>>>((float*)d_out);
}

// round 2
// speedup vs baseline: 1.2675x; 1.2675x over previous
#include <cuda_runtime.h>
#include <math.h>
#include <stdint.h>

// ---------------- problem constants ----------------
#define TT      512          // sequence length
#define UDIM    512          // LSTM hidden
#define NGATE   2048         // 4*U
#define XDIM    250          // word(200)+tag(50)
#define HID     1024
#define NSP     8192         // spans per head
#define KS_     4
#define KL_     3
#define TSZ     (TT*HID)     // one P table
#define GDIR    64           // CTAs per LSTM direction
#define UPC     8            // units per CTA (512/64)

// ---------------- device scratch (static; no allocation allowed) ----------------
__device__ float g_x   [TT*XDIM];
__device__ float g_xg  [4*TT*NGATE];     // gate preactivations (incl bias) per direction
__device__ float g_H0  [TT*1024];        // layer0 output [fwd|bwd]
__device__ float g_OUTF[TT*UDIM];        // layer1 fwd h
__device__ float g_OUTB[TT*UDIM];        // layer1 bwd h
__device__ float g_P   [14*TSZ];         // factorized span tables
__device__ float g_loss;
// 4 barrier counters (layer*2+dir), each on its own 128B line
__device__ unsigned g_cnt[4*32];

// ---------------- fast activations ----------------
__device__ __forceinline__ float fsigmoid(float x) {
    return __fdividef(1.f, 1.f + __expf(-x));
}
__device__ __forceinline__ float ftanh(float x) {
    return __fdividef(2.f, 1.f + __expf(-2.f * x)) - 1.f;
}

// ---------------- misc kernels ----------------
__global__ void zero_kernel() {
    g_loss = 0.f;
    #pragma unroll
    for (int i = 0; i < 4; i++) g_cnt[i * 32] = 0u;
}

__global__ void build_x_kernel(const int* __restrict__ wi, const int* __restrict__ ti,
                               const float* __restrict__ Ww, const float* __restrict__ Wt) {
    int t = blockIdx.x;
    int j = threadIdx.x;
    if (j < 200)      g_x[t*XDIM + j] = Ww[(size_t)wi[t]*200 + j];
    else if (j < XDIM) g_x[t*XDIM + j] = Wt[(size_t)ti[t]*50 + (j - 200)];
}

__global__ void finalize_kernel(float* out) {
    out[0] = g_loss * (1.0f / 16384.0f);
}

// ---------------- batched SGEMM: C = A(MxK) * B(NxK)^T (+bias[n]) ----------------
struct GemmDesc {
    const float* A; const float* B; float* C; const float* bias;
    int M, N, K, lda, ldb, ldc;
};
struct GemmBatch { GemmDesc d[14]; };

__global__ void __launch_bounds__(256)
sgemm_kernel(GemmBatch batch)
{
    GemmDesc g = batch.d[blockIdx.z];
    const int m0 = blockIdx.y * 64;
    const int n0 = blockIdx.x * 128;
    if (m0 >= g.M || n0 >= g.N) return;

    __shared__ float As[16][68];
    __shared__ float Bs[16][132];

    const int tid = threadIdx.x;
    const int tx = tid & 15;
    const int ty = tid >> 4;

    float acc[4][8];
    #pragma unroll
    for (int i = 0; i < 4; i++)
        #pragma unroll
        for (int j = 0; j < 8; j++) acc[i][j] = 0.f;

    for (int k0 = 0; k0 < g.K; k0 += 16) {
        {
            int m = tid >> 2;
            int kk = (tid & 3) * 4;
            const float* ap = g.A + (size_t)(m0 + m) * g.lda + k0 + kk;
            #pragma unroll
            for (int q = 0; q < 4; q++) {
                float v = (k0 + kk + q < g.K) ? ap[q] : 0.f;
                As[kk + q][m] = v;
            }
        }
        {
            int n = tid >> 1;
            int kk = (tid & 1) * 8;
            const float* bp = g.B + (size_t)(n0 + n) * g.ldb + k0 + kk;
            #pragma unroll
            for (int q = 0; q < 8; q++) {
                float v = (k0 + kk + q < g.K) ? bp[q] : 0.f;
                Bs[kk + q][n] = v;
            }
        }
        __syncthreads();

        #pragma unroll
        for (int kk = 0; kk < 16; kk++) {
            float a[4], b[8];
            *(float4*)a      = *(const float4*)&As[kk][ty * 4];
            *(float4*)&b[0]  = *(const float4*)&Bs[kk][tx * 8];
            *(float4*)&b[4]  = *(const float4*)&Bs[kk][tx * 8 + 4];
            #pragma unroll
            for (int i = 0; i < 4; i++)
                #pragma unroll
                for (int j = 0; j < 8; j++)
                    acc[i][j] = fmaf(a[i], b[j], acc[i][j]);
        }
        __syncthreads();
    }

    #pragma unroll
    for (int i = 0; i < 4; i++) {
        float* cp = g.C + (size_t)(m0 + ty * 4 + i) * g.ldc + n0 + tx * 8;
        float o[8];
        #pragma unroll
        for (int j = 0; j < 8; j++) {
            float v = acc[i][j];
            if (g.bias) v += g.bias[n0 + tx * 8 + j];
            o[j] = v;
        }
        *(float4*)cp       = *(float4*)&o[0];
        *(float4*)(cp + 4) = *(float4*)&o[4];
    }
}

// ---------------- persistent bidirectional LSTM layer ----------------
// 128 CTAs: blocks [0,64) forward, [64,128) backward. Each CTA owns 8 units
// (32 gate rows). Recurrent weights live in registers (64 floats/thread).
// Per-step sync: monotonic global counter per direction (no sleep, no reset).
__global__ void __launch_bounds__(256, 1)
lstm_kernel(const float* __restrict__ xgF, const float* __restrict__ xgB,
            const float* __restrict__ WhhF, const float* __restrict__ WhhB,
            float* outF, int strideF, int ocolF,
            float* outB, int strideB, int ocolB,
            int cbase)
{
    const int tid = threadIdx.x;
    const int bid = blockIdx.x;
    const bool back = (bid >= GDIR);
    const int dd    = back ? bid - GDIR : bid;

    const float* xg   = back ? xgB   : xgF;
    const float* Whh  = back ? WhhB  : WhhF;
    float*       out  = back ? outB  : outF;
    const int ostride = back ? strideB : strideF;
    const int ocol    = back ? ocolB  : ocolF;
    unsigned* cnt = &g_cnt[(cbase + (back ? 1 : 0)) * 32];

    const int row   = tid >> 3;   // 0..31  (gate*8 + unit_local)
    const int chunk = tid & 7;    // 0..7   (64-wide k chunk)
    const int gate  = row >> 3;
    const int ul    = row & 7;
    const int u0    = dd * UPC;
    const int ug    = u0 + ul;
    const int grow  = gate * UDIM + ug;

    // preload recurrent weights into registers (64 floats/thread)
    float4 w[16];
    {
        const float4* wp = (const float4*)(Whh + (size_t)grow * UDIM + chunk * 64);
        #pragma unroll
        for (int q = 0; q < 16; q++) w[q] = wp[q];
    }

    __shared__ float gs[32];
    float c = 0.f;
    const float* hbase = out + ocol;

    for (int s = 0; s < TT; s++) {
        const int t = back ? (TT - 1 - s) : s;

        // prefetch gate preactivations for this step (independent of h(s-1))
        float xgi = 0.f, xgf = 0.f, xgg = 0.f, xgo = 0.f;
        if (tid < UPC) {
            const float* xr = xg + (size_t)t * NGATE;
            const int u = u0 + tid;
            xgi = __ldg(xr + 0 * UDIM + u);
            xgf = __ldg(xr + 1 * UDIM + u);
            xgg = __ldg(xr + 2 * UDIM + u);
            xgo = __ldg(xr + 3 * UDIM + u);
        }

        if (s > 0) {
            if (tid == 0) {
                const unsigned target = (unsigned)s * GDIR;
                volatile unsigned* cp = (volatile unsigned*)cnt;
                while (*cp < target) { }
                __threadfence();
            }
            __syncthreads();
        }

        float a0 = 0.f, a1 = 0.f, a2 = 0.f, a3 = 0.f;
        if (s > 0) {
            const int tp = back ? t + 1 : t - 1;
            const float4* hp = (const float4*)(hbase + (size_t)tp * ostride + chunk * 64);
            #pragma unroll
            for (int q = 0; q < 16; q++) {
                float4 hv = __ldcg(hp + q);
                a0 = fmaf(w[q].x, hv.x, a0);
                a1 = fmaf(w[q].y, hv.y, a1);
                a2 = fmaf(w[q].z, hv.z, a2);
                a3 = fmaf(w[q].w, hv.w, a3);
            }
        }
        float acc = (a0 + a1) + (a2 + a3);
        acc += __shfl_xor_sync(0xffffffffu, acc, 1);
        acc += __shfl_xor_sync(0xffffffffu, acc, 2);
        acc += __shfl_xor_sync(0xffffffffu, acc, 4);
        if (chunk == 0) gs[row] = acc;
        __syncthreads();

        if (tid < UPC) {
            float gi = xgi + gs[0 * 8 + tid];
            float gf = xgf + gs[1 * 8 + tid];
            float gg = xgg + gs[2 * 8 + tid];
            float go = xgo + gs[3 * 8 + tid];
            float iv = fsigmoid(gi);
            float fv = fsigmoid(gf);
            float gv = ftanh(gg);
            float ov = fsigmoid(go);
            c = fv * c + iv * gv;
            float h = ov * ftanh(c);
            out[(size_t)t * ostride + ocol + u0 + tid] = h;
        }
        __syncthreads();
        if (tid == 0) {
            __threadfence();
            atomicAdd(cnt, 1u);
        }
    }
}

// ---------------- span loss: warp per span, gather from P tables ----------------
template<int KF, int NC>
__global__ void __launch_bounds__(256)
span_kernel(const int* __restrict__ lefts, const int* __restrict__ rights,
            const int* __restrict__ targets,
            const float* __restrict__ b1, const float* __restrict__ W2,
            const float* __restrict__ b2, int tabF, int tabB)
{
    const int warp = (blockIdx.x * blockDim.x + threadIdx.x) >> 5;
    const int lane = threadIdx.x & 31;
    const int wInB = threadIdx.x >> 5;

    float4 acc[8];
    #pragma unroll
    for (int m = 0; m < 8; m++)
        acc[m] = *(const float4*)(b1 + m * 128 + lane * 4);

    int ls[KF], rs[KF];
    #pragma unroll
    for (int k = 0; k < KF; k++) {
        ls[k] = __ldg(lefts  + (size_t)warp * KF + k);
        rs[k] = __ldg(rights + (size_t)warp * KF + k);
    }

    #pragma unroll
    for (int k = 0; k < KF; k++) {
        const float* Pf = g_P + (size_t)(tabF + k) * TSZ;
        const float* Pb = g_P + (size_t)(tabB + k) * TSZ;
        const float* r0 = Pf + (size_t)rs[k]       * HID + lane * 4;
        const float* r1 = Pf + (size_t)(ls[k] - 1) * HID + lane * 4;
        const float* r2 = Pb + (size_t)ls[k]       * HID + lane * 4;
        const float* r3 = Pb + (size_t)(rs[k] + 1) * HID + lane * 4;
        #pragma unroll
        for (int m = 0; m < 8; m++) {
            float4 va = __ldg((const float4*)(r0 + m * 128));
            float4 vb = __ldg((const float4*)(r1 + m * 128));
            float4 vc = __ldg((const float4*)(r2 + m * 128));
            float4 vd = __ldg((const float4*)(r3 + m * 128));
            acc[m].x += (va.x - vb.x) + (vc.x - vd.x);
            acc[m].y += (va.y - vb.y) + (vc.y - vd.y);
            acc[m].z += (va.z - vb.z) + (vc.z - vd.z);
            acc[m].w += (va.w - vb.w) + (vc.w - vd.w);
        }
    }
    #pragma unroll
    for (int m = 0; m < 8; m++) {
        acc[m].x = fmaxf(acc[m].x, 0.f);
        acc[m].y = fmaxf(acc[m].y, 0.f);
        acc[m].z = fmaxf(acc[m].z, 0.f);
        acc[m].w = fmaxf(acc[m].w, 0.f);
    }

    const int tgt = __ldg(targets + warp);
    float mx = -1e30f, ssum = 0.f, sct = 0.f;
    for (int s = 0; s < NC; s++) {
        const float* wr = W2 + (size_t)s * HID + lane * 4;
        float p = 0.f;
        #pragma unroll
        for (int m = 0; m < 8; m++) {
            float4 wv = __ldg((const float4*)(wr + m * 128));
            p += wv.x * acc[m].x + wv.y * acc[m].y + wv.z * acc[m].z + wv.w * acc[m].w;
        }
        p += __shfl_xor_sync(0xffffffffu, p, 1);
        p += __shfl_xor_sync(0xffffffffu, p, 2);
        p += __shfl_xor_sync(0xffffffffu, p, 4);
        p += __shfl_xor_sync(0xffffffffu, p, 8);
        p += __shfl_xor_sync(0xffffffffu, p, 16);
        p += b2[s];
        if (s == tgt) sct = p;
        float m2 = fmaxf(mx, p);
        ssum = ssum * expf(mx - m2) + expf(p - m2);
        mx = m2;
    }
    float loss = mx + logf(ssum) - sct;

    __shared__ float smloss[8];
    if (lane == 0) smloss[wInB] = loss;
    __syncthreads();
    if (threadIdx.x == 0) {
        float s = 0.f;
        #pragma unroll
        for (int q = 0; q < 8; q++) s += smloss[q];
        atomicAdd(&g_loss, s);
    }
}

// ---------------- host launch ----------------
extern "C" void kernel_launch(void* const* d_in, const int* in_sizes, int n_in,
                              void* d_out, int out_size)
{
    (void)n_in; (void)out_size;
    const int* wi = (const int*)d_in[0];
    const int* ti = (const int*)d_in[1];

    int isl, isr, ist, ill, ilr, ilt;
    if (in_sizes[2] == NSP) {
        ist = 2; ilt = 3; isl = 4; isr = 5; ill = 6; ilr = 7;
    } else {
        isl = 2; isr = 3; ist = 4; ill = 5; ilr = 6; ilt = 7;
    }

    const float* Wih[4] = {(const float*)d_in[10], (const float*)d_in[13],
                           (const float*)d_in[16], (const float*)d_in[19]};
    const float* Whh[4] = {(const float*)d_in[11], (const float*)d_in[14],
                           (const float*)d_in[17], (const float*)d_in[20]};
    const float* bb [4] = {(const float*)d_in[12], (const float*)d_in[15],
                           (const float*)d_in[18], (const float*)d_in[21]};
    const float* Ws1 = (const float*)d_in[22];
    const float* bs1 = (const float*)d_in[23];
    const float* Ws2 = (const float*)d_in[24];
    const float* bs2 = (const float*)d_in[25];
    const float* Wl1 = (const float*)d_in[26];
    const float* bl1 = (const float*)d_in[27];
    const float* Wl2 = (const float*)d_in[28];
    const float* bl2 = (const float*)d_in[29];

    float *px, *pxg, *pH0, *pOF, *pOB, *pP;
    cudaGetSymbolAddress((void**)&px,  g_x);
    cudaGetSymbolAddress((void**)&pxg, g_xg);
    cudaGetSymbolAddress((void**)&pH0, g_H0);
    cudaGetSymbolAddress((void**)&pOF, g_OUTF);
    cudaGetSymbolAddress((void**)&pOB, g_OUTB);
    cudaGetSymbolAddress((void**)&pP,  g_P);

    zero_kernel<<<1, 1>>>();
    build_x_kernel<<<TT, 256>>>(wi, ti, (const float*)d_in[8], (const float*)d_in[9]);

    // layer0 gate preactivations: xg = x @ Wih^T + b   (2 directions batched)
    {
        GemmBatch gb = {};
        for (int d = 0; d < 2; d++)
            gb.d[d] = { px, Wih[d], pxg + (size_t)d * TT * NGATE, bb[d],
                        TT, NGATE, XDIM, XDIM, XDIM, NGATE };
        sgemm_kernel<<<dim3(16, 8, 2), 256>>>(gb);
    }
    lstm_kernel<<<2 * GDIR, 256>>>(pxg, pxg + (size_t)TT * NGATE,
                                   Whh[0], Whh[1],
                                   pH0, 1024, 0, pH0, 1024, 512, 0);
    // layer1 gate preactivations from H0
    {
        GemmBatch gb = {};
        for (int d = 0; d < 2; d++)
            gb.d[d] = { pH0, Wih[2 + d], pxg + (size_t)(2 + d) * TT * NGATE, bb[2 + d],
                        TT, NGATE, 1024, 1024, 1024, NGATE };
        sgemm_kernel<<<dim3(16, 8, 2), 256>>>(gb);
    }
    lstm_kernel<<<2 * GDIR, 256>>>(pxg + (size_t)2 * TT * NGATE, pxg + (size_t)3 * TT * NGATE,
                                   Whh[2], Whh[3],
                                   pOF, 512, 0, pOB, 512, 0, 2);

    // factorized span tables: P_k = out_dir @ W1_block_k^T  (14 batched GEMMs)
    {
        GemmBatch gb = {};
        for (int k = 0; k < KS_; k++) {
            gb.d[k]       = { pOF, Ws1 + k * 512,        pP + (size_t)k * TSZ,        nullptr,
                              TT, HID, 512, 512, 4096, HID };
            gb.d[4 + k]   = { pOB, Ws1 + 2048 + k * 512, pP + (size_t)(4 + k) * TSZ,  nullptr,
                              TT, HID, 512, 512, 4096, HID };
        }
        for (int k = 0; k < KL_; k++) {
            gb.d[8 + k]   = { pOF, Wl1 + k * 512,        pP + (size_t)(8 + k) * TSZ,  nullptr,
                              TT, HID, 512, 512, 3072, HID };
            gb.d[11 + k]  = { pOB, Wl1 + 1536 + k * 512, pP + (size_t)(11 + k) * TSZ, nullptr,
                              TT, HID, 512, 512, 3072, HID };
        }
        sgemm_kernel<<<dim3(8, 8, 14), 256>>>(gb);
    }

    span_kernel<KS_, 2 ><<<NSP / 8, 256>>>((const int*)d_in[isl], (const int*)d_in[isr],
                                           (const int*)d_in[ist], bs1, Ws2, bs2, 0, 4);
    span_kernel<KL_, 56><<<NSP / 8, 256>>>((const int*)d_in[ill], (const int*)d_in[ilr],
                                           (const int*)d_in[ilt], bl1, Wl2, bl2, 8, 11);

    finalize_kernel<<<1, 1>>>((float*)d_out);
}

// round 3
// speedup vs baseline: 3.2016x; 2.5260x over previous
#include <cuda_runtime.h>
#include <math.h>
#include <stdint.h>

// ---------------- problem constants ----------------
#define TT      512          // sequence length
#define UDIM    512          // LSTM hidden
#define NGATE   2048         // 4*U
#define XDIM    250          // word(200)+tag(50)
#define HID     1024
#define NSP     8192         // spans per head
#define KS_     4
#define KL_     3
#define TSZ     (TT*HID)     // one P table
#define GDIR    32           // CTAs per LSTM direction
#define UPC     16           // units per CTA (512/32)
#define FSTR    8            // flag stride in uints (32B)

// ---------------- device scratch (static; no allocation allowed) ----------------
__device__ float g_x   [TT*XDIM];
__device__ float g_xg  [4*TT*NGATE];     // gate preactivations (incl bias) per direction
__device__ float g_H0  [TT*1024];        // layer0 output [fwd|bwd]
__device__ float g_OUTF[TT*UDIM];        // layer1 fwd h
__device__ float g_OUTB[TT*UDIM];        // layer1 bwd h
__device__ float g_P   [14*TSZ];         // factorized span tables
__device__ float g_loss;
// 4 flag sets (layer*2+dir), 32 flags each, 32B apart
__device__ unsigned g_flag[4*GDIR*FSTR];

// ---------------- fast activations ----------------
__device__ __forceinline__ float fsigmoid(float x) {
    return __fdividef(1.f, 1.f + __expf(-x));
}
__device__ __forceinline__ float ftanh(float x) {
    return __fdividef(2.f, 1.f + __expf(-2.f * x)) - 1.f;
}

// ---------------- misc kernels ----------------
__global__ void zero_kernel() {
    g_loss = 0.f;
    int i = threadIdx.x;
    if (i < 4 * GDIR) g_flag[i * FSTR] = 0u;
}

__global__ void build_x_kernel(const int* __restrict__ wi, const int* __restrict__ ti,
                               const float* __restrict__ Ww, const float* __restrict__ Wt) {
    int t = blockIdx.x;
    int j = threadIdx.x;
    if (j < 200)      g_x[t*XDIM + j] = Ww[(size_t)wi[t]*200 + j];
    else if (j < XDIM) g_x[t*XDIM + j] = Wt[(size_t)ti[t]*50 + (j - 200)];
}

__global__ void finalize_kernel(float* out) {
    out[0] = g_loss * (1.0f / 16384.0f);
}

// ---------------- batched SGEMM: C = A(MxK) * B(NxK)^T (+bias[n]) ----------------
struct GemmDesc {
    const float* A; const float* B; float* C; const float* bias;
    int M, N, K, lda, ldb, ldc;
};
struct GemmBatch { GemmDesc d[14]; };

__global__ void __launch_bounds__(256)
sgemm_kernel(GemmBatch batch)
{
    GemmDesc g = batch.d[blockIdx.z];
    const int m0 = blockIdx.y * 64;
    const int n0 = blockIdx.x * 128;
    if (m0 >= g.M || n0 >= g.N) return;

    __shared__ float As[16][68];
    __shared__ float Bs[16][132];

    const int tid = threadIdx.x;
    const int tx = tid & 15;
    const int ty = tid >> 4;

    float acc[4][8];
    #pragma unroll
    for (int i = 0; i < 4; i++)
        #pragma unroll
        for (int j = 0; j < 8; j++) acc[i][j] = 0.f;

    for (int k0 = 0; k0 < g.K; k0 += 16) {
        {
            int m = tid >> 2;
            int kk = (tid & 3) * 4;
            const float* ap = g.A + (size_t)(m0 + m) * g.lda + k0 + kk;
            #pragma unroll
            for (int q = 0; q < 4; q++) {
                float v = (k0 + kk + q < g.K) ? ap[q] : 0.f;
                As[kk + q][m] = v;
            }
        }
        {
            int n = tid >> 1;
            int kk = (tid & 1) * 8;
            const float* bp = g.B + (size_t)(n0 + n) * g.ldb + k0 + kk;
            #pragma unroll
            for (int q = 0; q < 8; q++) {
                float v = (k0 + kk + q < g.K) ? bp[q] : 0.f;
                Bs[kk + q][n] = v;
            }
        }
        __syncthreads();

        #pragma unroll
        for (int kk = 0; kk < 16; kk++) {
            float a[4], b[8];
            *(float4*)a      = *(const float4*)&As[kk][ty * 4];
            *(float4*)&b[0]  = *(const float4*)&Bs[kk][tx * 8];
            *(float4*)&b[4]  = *(const float4*)&Bs[kk][tx * 8 + 4];
            #pragma unroll
            for (int i = 0; i < 4; i++)
                #pragma unroll
                for (int j = 0; j < 8; j++)
                    acc[i][j] = fmaf(a[i], b[j], acc[i][j]);
        }
        __syncthreads();
    }

    #pragma unroll
    for (int i = 0; i < 4; i++) {
        float* cp = g.C + (size_t)(m0 + ty * 4 + i) * g.ldc + n0 + tx * 8;
        float o[8];
        #pragma unroll
        for (int j = 0; j < 8; j++) {
            float v = acc[i][j];
            if (g.bias) v += g.bias[n0 + tx * 8 + j];
            o[j] = v;
        }
        *(float4*)cp       = *(float4*)&o[0];
        *(float4*)(cp + 4) = *(float4*)&o[4];
    }
}

// ---------------- persistent bidirectional LSTM layer ----------------
// 64 CTAs: blocks [0,32) forward, [32,64) backward. Each CTA owns 16 units
// (64 gate rows). Warp layout: warp = (row_group, k_chunk); all 32 lanes of a
// warp read the SAME h address (broadcast LDG, nL=1). Per-step sync via
// per-CTA flag array (no shared-counter atomics).
__global__ void __launch_bounds__(512, 1)
lstm_kernel(const float* __restrict__ xgF, const float* __restrict__ xgB,
            const float* __restrict__ WhhF, const float* __restrict__ WhhB,
            float* outF, int strideF, int ocolF,
            float* outB, int strideB, int ocolB,
            int cbase)
{
    const int tid  = threadIdx.x;
    const int bid  = blockIdx.x;
    const bool back = (bid >= GDIR);
    const int dd    = back ? bid - GDIR : bid;

    const float* xg   = back ? xgB   : xgF;
    const float* Whh  = back ? WhhB  : WhhF;
    float*       out  = back ? outB  : outF;
    const int ostride = back ? strideB : strideF;
    const int ocol    = back ? ocolB  : ocolF;
    unsigned* flags = &g_flag[(size_t)(cbase + (back ? 1 : 0)) * GDIR * FSTR];

    const int wid   = tid >> 5;
    const int lane  = tid & 31;
    const int rg    = wid & 1;        // row group (0/1)
    const int chunk = wid >> 1;       // 0..7 (64-wide k chunk)
    const int row   = rg * 32 + lane; // 0..63
    const int gate  = row >> 4;
    const int ul    = row & 15;
    const int u0    = dd * UPC;
    const int grow  = gate * UDIM + u0 + ul;

    // preload recurrent weights: 64 floats/thread
    float4 w[16];
    {
        const float4* wp = (const float4*)(Whh + (size_t)grow * UDIM + chunk * 64);
        #pragma unroll
        for (int q = 0; q < 16; q++) w[q] = wp[q];
    }

    __shared__ float part[8][64];
    float c = 0.f;
    const float* hbase = out + ocol;

    for (int s = 0; s < TT; s++) {
        const int t = back ? (TT - 1 - s) : s;

        // prefetch gate preactivations (independent of h(s-1))
        float xgi = 0.f, xgf = 0.f, xgg = 0.f, xgo = 0.f;
        if (tid < UPC) {
            const float* xr = xg + (size_t)t * NGATE;
            const int u = u0 + tid;
            xgi = __ldg(xr + 0 * UDIM + u);
            xgf = __ldg(xr + 1 * UDIM + u);
            xgg = __ldg(xr + 2 * UDIM + u);
            xgo = __ldg(xr + 3 * UDIM + u);
        }

        if (s > 0) {
            if (wid == 0) {
                volatile const unsigned* fp = flags + lane * FSTR;
                const unsigned target = (unsigned)s;
                unsigned v;
                do { v = *fp; } while (!__all_sync(0xffffffffu, v >= target));
                __threadfence();
            }
            __syncthreads();
        }

        float a0 = 0.f, a1 = 0.f, a2 = 0.f, a3 = 0.f;
        if (s > 0) {
            const int tp = back ? t + 1 : t - 1;
            // all lanes of this warp read the same address -> broadcast
            const float4* hp = (const float4*)(hbase + (size_t)tp * ostride + chunk * 64);
            #pragma unroll
            for (int q = 0; q < 16; q++) {
                float4 hv = __ldcg(hp + q);
                a0 = fmaf(w[q].x, hv.x, a0);
                a1 = fmaf(w[q].y, hv.y, a1);
                a2 = fmaf(w[q].z, hv.z, a2);
                a3 = fmaf(w[q].w, hv.w, a3);
            }
        }
        part[chunk][row] = (a0 + a1) + (a2 + a3);
        __syncthreads();

        if (tid < UPC) {
            float gi = xgi, gf = xgf, gg = xgg, go = xgo;
            #pragma unroll
            for (int cc = 0; cc < 8; cc++) {
                gi += part[cc][ 0 + tid];
                gf += part[cc][16 + tid];
                gg += part[cc][32 + tid];
                go += part[cc][48 + tid];
            }
            float iv = fsigmoid(gi);
            float fv = fsigmoid(gf);
            float gv = ftanh(gg);
            float ov = fsigmoid(go);
            c = fv * c + iv * gv;
            float h = ov * ftanh(c);
            out[(size_t)t * ostride + ocol + u0 + tid] = h;
        }
        __syncthreads();           // all h stores issued CTA-wide
        if (tid == 0) {
            __threadfence();       // h visible at L2 before flag
            atomicExch(flags + dd * FSTR, (unsigned)(s + 1));
        }
    }
}

// ---------------- span loss: warp per span, gather from P tables ----------------
template<int KF, int NC>
__global__ void __launch_bounds__(256)
span_kernel(const int* __restrict__ lefts, const int* __restrict__ rights,
            const int* __restrict__ targets,
            const float* __restrict__ b1, const float* __restrict__ W2,
            const float* __restrict__ b2, int tabF, int tabB)
{
    const int warp = (blockIdx.x * blockDim.x + threadIdx.x) >> 5;
    const int lane = threadIdx.x & 31;
    const int wInB = threadIdx.x >> 5;

    float4 acc[8];
    #pragma unroll
    for (int m = 0; m < 8; m++)
        acc[m] = *(const float4*)(b1 + m * 128 + lane * 4);

    int ls[KF], rs[KF];
    #pragma unroll
    for (int k = 0; k < KF; k++) {
        ls[k] = __ldg(lefts  + (size_t)warp * KF + k);
        rs[k] = __ldg(rights + (size_t)warp * KF + k);
    }

    #pragma unroll
    for (int k = 0; k < KF; k++) {
        const float* Pf = g_P + (size_t)(tabF + k) * TSZ;
        const float* Pb = g_P + (size_t)(tabB + k) * TSZ;
        const float* r0 = Pf + (size_t)rs[k]       * HID + lane * 4;
        const float* r1 = Pf + (size_t)(ls[k] - 1) * HID + lane * 4;
        const float* r2 = Pb + (size_t)ls[k]       * HID + lane * 4;
        const float* r3 = Pb + (size_t)(rs[k] + 1) * HID + lane * 4;
        #pragma unroll
        for (int m = 0; m < 8; m++) {
            float4 va = __ldg((const float4*)(r0 + m * 128));
            float4 vb = __ldg((const float4*)(r1 + m * 128));
            float4 vc = __ldg((const float4*)(r2 + m * 128));
            float4 vd = __ldg((const float4*)(r3 + m * 128));
            acc[m].x += (va.x - vb.x) + (vc.x - vd.x);
            acc[m].y += (va.y - vb.y) + (vc.y - vd.y);
            acc[m].z += (va.z - vb.z) + (vc.z - vd.z);
            acc[m].w += (va.w - vb.w) + (vc.w - vd.w);
        }
    }
    #pragma unroll
    for (int m = 0; m < 8; m++) {
        acc[m].x = fmaxf(acc[m].x, 0.f);
        acc[m].y = fmaxf(acc[m].y, 0.f);
        acc[m].z = fmaxf(acc[m].z, 0.f);
        acc[m].w = fmaxf(acc[m].w, 0.f);
    }

    const int tgt = __ldg(targets + warp);
    float mx = -1e30f, ssum = 0.f, sct = 0.f;
    for (int s = 0; s < NC; s++) {
        const float* wr = W2 + (size_t)s * HID + lane * 4;
        float p = 0.f;
        #pragma unroll
        for (int m = 0; m < 8; m++) {
            float4 wv = __ldg((const float4*)(wr + m * 128));
            p += wv.x * acc[m].x + wv.y * acc[m].y + wv.z * acc[m].z + wv.w * acc[m].w;
        }
        p += __shfl_xor_sync(0xffffffffu, p, 1);
        p += __shfl_xor_sync(0xffffffffu, p, 2);
        p += __shfl_xor_sync(0xffffffffu, p, 4);
        p += __shfl_xor_sync(0xffffffffu, p, 8);
        p += __shfl_xor_sync(0xffffffffu, p, 16);
        p += b2[s];
        if (s == tgt) sct = p;
        float m2 = fmaxf(mx, p);
        ssum = ssum * expf(mx - m2) + expf(p - m2);
        mx = m2;
    }
    float loss = mx + logf(ssum) - sct;

    __shared__ float smloss[8];
    if (lane == 0) smloss[wInB] = loss;
    __syncthreads();
    if (threadIdx.x == 0) {
        float s = 0.f;
        #pragma unroll
        for (int q = 0; q < 8; q++) s += smloss[q];
        atomicAdd(&g_loss, s);
    }
}

// ---------------- host launch ----------------
extern "C" void kernel_launch(void* const* d_in, const int* in_sizes, int n_in,
                              void* d_out, int out_size)
{
    (void)n_in; (void)out_size;
    const int* wi = (const int*)d_in[0];
    const int* ti = (const int*)d_in[1];

    int isl, isr, ist, ill, ilr, ilt;
    if (in_sizes[2] == NSP) {
        ist = 2; ilt = 3; isl = 4; isr = 5; ill = 6; ilr = 7;
    } else {
        isl = 2; isr = 3; ist = 4; ill = 5; ilr = 6; ilt = 7;
    }

    const float* Wih[4] = {(const float*)d_in[10], (const float*)d_in[13],
                           (const float*)d_in[16], (const float*)d_in[19]};
    const float* Whh[4] = {(const float*)d_in[11], (const float*)d_in[14],
                           (const float*)d_in[17], (const float*)d_in[20]};
    const float* bb [4] = {(const float*)d_in[12], (const float*)d_in[15],
                           (const float*)d_in[18], (const float*)d_in[21]};
    const float* Ws1 = (const float*)d_in[22];
    const float* bs1 = (const float*)d_in[23];
    const float* Ws2 = (const float*)d_in[24];
    const float* bs2 = (const float*)d_in[25];
    const float* Wl1 = (const float*)d_in[26];
    const float* bl1 = (const float*)d_in[27];
    const float* Wl2 = (const float*)d_in[28];
    const float* bl2 = (const float*)d_in[29];

    float *px, *pxg, *pH0, *pOF, *pOB, *pP;
    cudaGetSymbolAddress((void**)&px,  g_x);
    cudaGetSymbolAddress((void**)&pxg, g_xg);
    cudaGetSymbolAddress((void**)&pH0, g_H0);
    cudaGetSymbolAddress((void**)&pOF, g_OUTF);
    cudaGetSymbolAddress((void**)&pOB, g_OUTB);
    cudaGetSymbolAddress((void**)&pP,  g_P);

    zero_kernel<<<1, 256>>>();
    build_x_kernel<<<TT, 256>>>(wi, ti, (const float*)d_in[8], (const float*)d_in[9]);

    // layer0 gate preactivations: xg = x @ Wih^T + b   (2 directions batched)
    {
        GemmBatch gb = {};
        for (int d = 0; d < 2; d++)
            gb.d[d] = { px, Wih[d], pxg + (size_t)d * TT * NGATE, bb[d],
                        TT, NGATE, XDIM, XDIM, XDIM, NGATE };
        sgemm_kernel<<<dim3(16, 8, 2), 256>>>(gb);
    }
    lstm_kernel<<<2 * GDIR, 512>>>(pxg, pxg + (size_t)TT * NGATE,
                                   Whh[0], Whh[1],
                                   pH0, 1024, 0, pH0, 1024, 512, 0);
    // layer1 gate preactivations from H0
    {
        GemmBatch gb = {};
        for (int d = 0; d < 2; d++)
            gb.d[d] = { pH0, Wih[2 + d], pxg + (size_t)(2 + d) * TT * NGATE, bb[2 + d],
                        TT, NGATE, 1024, 1024, 1024, NGATE };
        sgemm_kernel<<<dim3(16, 8, 2), 256>>>(gb);
    }
    lstm_kernel<<<2 * GDIR, 512>>>(pxg + (size_t)2 * TT * NGATE, pxg + (size_t)3 * TT * NGATE,
                                   Whh[2], Whh[3],
                                   pOF, 512, 0, pOB, 512, 0, 2);

    // factorized span tables: P_k = out_dir @ W1_block_k^T  (14 batched GEMMs)
    {
        GemmBatch gb = {};
        for (int k = 0; k < KS_; k++) {
            gb.d[k]       = { pOF, Ws1 + k * 512,        pP + (size_t)k * TSZ,        nullptr,
                              TT, HID, 512, 512, 4096, HID };
            gb.d[4 + k]   = { pOB, Ws1 + 2048 + k * 512, pP + (size_t)(4 + k) * TSZ,  nullptr,
                              TT, HID, 512, 512, 4096, HID };
        }
        for (int k = 0; k < KL_; k++) {
            gb.d[8 + k]   = { pOF, Wl1 + k * 512,        pP + (size_t)(8 + k) * TSZ,  nullptr,
                              TT, HID, 512, 512, 3072, HID };
            gb.d[11 + k]  = { pOB, Wl1 + 1536 + k * 512, pP + (size_t)(11 + k) * TSZ, nullptr,
                              TT, HID, 512, 512, 3072, HID };
        }
        sgemm_kernel<<<dim3(8, 8, 14), 256>>>(gb);
    }

    span_kernel<KS_, 2 ><<<NSP / 8, 256>>>((const int*)d_in[isl], (const int*)d_in[isr],
                                           (const int*)d_in[ist], bs1, Ws2, bs2, 0, 4);
    span_kernel<KL_, 56><<<NSP / 8, 256>>>((const int*)d_in[ill], (const int*)d_in[ilr],
                                           (const int*)d_in[ilt], bl1, Wl2, bl2, 8, 11);

    finalize_kernel<<<1, 1>>>((float*)d_out);
}